// round 4
// baseline (speedup 1.0000x reference)
#include <cuda_runtime.h>

// MedianFilter: xs [B=4,T=32,N=128,D=32] f32, A [1,128,128] i32.
// Per (b,t,n,d): lower median over {prev-self (t>0), next-self (t<T-1),
//   xs[b,t,j,d] for j with (A+I)[n][j]!=0}.
// Exact: two uniform 4-bit histogram scans (-> exact 8-bit prefix), collect
// the few 8-bit-prefix matches, tiny nibble radix tail. Adjacency compacted
// once in a prep kernel (shared by all frames). Quad-packed index lists.

#define Bc 4
#define Tc 32
#define Nc 128
#define Dc 32
#define NTH 128          // threads per main block (4 warps)
#define NODES_PB 16      // nodes per block
#define SLOTS 16
#define ROWP 132         // padded nbr row stride (multiple of 4, >= 128+3)

__device__ unsigned char g_nbr[Nc * ROWP];
__device__ int g_cnt[Nc];

__device__ __forceinline__ unsigned f2u(float f) {
    unsigned s = __float_as_uint(f);
    return s ^ ((unsigned)((int)s >> 31) | 0x80000000u);
}
__device__ __forceinline__ float u2f(unsigned u) {
    unsigned s = (u & 0x80000000u) ? (u ^ 0x80000000u) : ~u;
    return __uint_as_float(s);
}

// Select nibble bin containing rank m from byte-packed histograms
// h0 (bins 0-7) / h1 (bins 8-15). Total count <= ~133, bytes don't overflow.
__device__ __forceinline__ int select_bin(unsigned long long h0,
                                          unsigned long long h1,
                                          unsigned &m, unsigned &rem)
{
    unsigned long long s0 = h0 * 0x0101010101010101ull;
    unsigned total0 = (unsigned)(s0 >> 56);
    unsigned long long S, H;
    int base;
    unsigned mm = m;
    if (mm < total0) { S = s0; H = h0; base = 0; }
    else {
        mm -= total0;
        S = h1 * 0x0101010101010101ull; H = h1; base = 8;
    }
    int g = 0;
    if ((unsigned)((S >> 24) & 0xFF) <= mm) g = 4;
    if ((unsigned)((S >> (8 * (g + 1))) & 0xFF) <= mm) g += 2;
    if ((unsigned)((S >> (8 * g)) & 0xFF) <= mm) g += 1;
    unsigned before = g ? (unsigned)((S >> (8 * (g - 1))) & 0xFF) : 0u;
    rem = (unsigned)((H >> (8 * g)) & 0xFF);
    m = mm - before;
    return base + g;
}

#define HIST(u_)                                                    \
    {                                                               \
        unsigned nib_ = ((u_) >> shift) & 15u;                      \
        unsigned long long inc_ = 1ull << ((nib_ & 7u) * 8u);       \
        if (nib_ & 8u) h1 += inc_; else h0 += inc_;                 \
    }

#define HISTF(u_)                                                   \
    {                                                               \
        unsigned u__ = (u_);                                        \
        bool match_ = ((u__ ^ prefix) >> (shift + 4)) == 0u;        \
        unsigned nib_ = (u__ >> shift) & 15u;                       \
        unsigned long long inc_ =                                   \
            match_ ? (1ull << ((nib_ & 7u) * 8u)) : 0ull;           \
        if (nib_ & 8u) h1 += inc_; else h0 += inc_;                 \
    }

__global__ void prep_kernel(const int* __restrict__ A)
{
    const int n = threadIdx.x;          // 128 threads, one row each
    const int* row = A + n * Nc;
    int c = 0;
    #pragma unroll 4
    for (int j = 0; j < Nc; j++)
        if (row[j] != 0 || j == n) g_nbr[n * ROWP + (c++)] = (unsigned char)j;
    g_cnt[n] = c;
    while (c & 3) g_nbr[n * ROWP + (c++)] = (unsigned char)Nc;  // pad -> dummy row
}

__global__ __launch_bounds__(NTH, 8)
void median_kernel(const float* __restrict__ xs,
                   float* __restrict__ out)
{
    __shared__ unsigned tile[(Nc + 1) * Dc];          // +1 dummy row (~16.1KB)
    __shared__ unsigned char nbr[NODES_PB * ROWP];    // ~2.1KB
    __shared__ int cnt[NODES_PB];
    __shared__ unsigned buf[SLOTS * NTH];             // 8KB

    const int bid  = blockIdx.x;
    const int bt   = bid >> 3;             // 0..127
    const int oct  = bid & 7;              // node group of 16
    const int t    = bt & (Tc - 1);
    const int tid  = threadIdx.x;
    const int lane = tid & 31;
    const int w    = tid >> 5;             // 0..3
    const int nbase = oct * NODES_PB;

    // load + transform frame tile; fill dummy row with max key
    const float* cur = xs + (size_t)bt * (Nc * Dc);
    #pragma unroll
    for (int i = tid; i < Nc * Dc; i += NTH) tile[i] = f2u(cur[i]);
    tile[Nc * Dc + tid % Dc] = 0xFFFFFFFFu;   // covers all 32 dummy entries

    // copy this block's neighbor rows + counts from global
    {
        const unsigned* src = (const unsigned*)&g_nbr[nbase * ROWP];
        unsigned* dst = (unsigned*)nbr;
        #pragma unroll
        for (int i = tid; i < NODES_PB * ROWP / 4; i += NTH) dst[i] = src[i];
        if (tid < NODES_PB) cnt[tid] = g_cnt[nbase + tid];
    }
    __syncthreads();

    const bool hasPrev = (t > 0);
    const bool hasNext = (t < Tc - 1);
    const float* prevp = xs + (size_t)(bt - 1) * (Nc * Dc);
    const float* nextp = xs + (size_t)(bt + 1) * (Nc * Dc);

    #pragma unroll 1
    for (int it = 0; it < NODES_PB / 4; it++) {
        const int nl = w * 4 + it;                 // local node 0..15
        const int n  = nbase + nl;
        const int k  = cnt[nl];
        const int kq = (k + 3) >> 2;               // quads (padded)
        const unsigned pad = (unsigned)(kq * 4 - k);
        const unsigned char* lst = &nbr[nl * ROWP];
        const unsigned* lstw = (const unsigned*)lst;
        const int ktot = k + (int)hasPrev + (int)hasNext;
        unsigned m = (unsigned)((ktot - 1) >> 1);

        const unsigned prevU = hasPrev ? f2u(prevp[n * Dc + lane]) : 0u;
        const unsigned nextU = hasNext ? f2u(nextp[n * Dc + lane]) : 0u;

        // ---- scan 1: nibble @28, quad-packed ----
        unsigned g1, rem1;
        {
            const int shift = 28;
            unsigned long long h0 = 0ull, h1 = 0ull;
            for (int q = 0; q < kq; q++) {
                unsigned w4 = lstw[q];
                #pragma unroll
                for (int s = 0; s < 4; s++) {
                    unsigned idx = (w4 >> (8 * s)) & 255u;
                    unsigned u = tile[(idx << 5) | lane];
                    HIST(u);
                }
            }
            if (hasPrev) HIST(prevU);
            if (hasNext) HIST(nextU);
            h1 -= (unsigned long long)pad << 56;     // remove dummy (bin 15)
            g1 = (unsigned)select_bin(h0, h1, m, rem1);
        }

        // ---- scan 2: nibble @24, filtered on top nibble, quad-packed ----
        unsigned g2, rem2;
        {
            const int shift = 24;
            const unsigned prefix = g1 << 28;
            unsigned long long h0 = 0ull, h1 = 0ull;
            for (int q = 0; q < kq; q++) {
                unsigned w4 = lstw[q];
                #pragma unroll
                for (int s = 0; s < 4; s++) {
                    unsigned idx = (w4 >> (8 * s)) & 255u;
                    unsigned u = tile[(idx << 5) | lane];
                    HISTF(u);
                }
            }
            if (hasPrev) HISTF(prevU);
            if (hasNext) HISTF(nextU);
            if (g1 == 15u) h1 -= (unsigned long long)pad << 56;  // dummy matched
            g2 = (unsigned)select_bin(h0, h1, m, rem2);
        }
        const unsigned pref8 = (g1 << 4) | g2;

        // ---- collect 8-bit-prefix matches ----
        int c = 0;
        for (int i = 0; i < k; i++) {
            unsigned u = tile[(((int)lst[i]) << 5) | lane];
            if ((u >> 24) == pref8) {
                if (c < SLOTS) buf[c * NTH + tid] = u;
                c++;
            }
        }
        if (hasPrev && (prevU >> 24) == pref8) { if (c < SLOTS) buf[c * NTH + tid] = prevU; c++; }
        if (hasNext && (nextU >> 24) == pref8) { if (c < SLOTS) buf[c * NTH + tid] = nextU; c++; }

        unsigned result;
        const bool ovf = (c > SLOTS);

        if (__any_sync(0xFFFFFFFFu, ovf)) {
            // rare exact fallback: filtered full scans on lower nibbles
            if (ovf) {
                unsigned prefix = pref8 << 24;
                bool done = false;
                #pragma unroll 1
                for (int p = 2; p < 8 && !done; p++) {
                    const int shift = 28 - 4 * p;
                    unsigned long long h0 = 0ull, h1 = 0ull;
                    for (int i = 0; i < k; i++) {
                        unsigned u = tile[(((int)lst[i]) << 5) | lane];
                        HISTF(u);
                    }
                    if (hasPrev) HISTF(prevU);
                    if (hasNext) HISTF(nextU);
                    unsigned rem;
                    int g = select_bin(h0, h1, m, rem);
                    prefix |= (unsigned)g << shift;
                    if (rem == 1u) {
                        unsigned r = prefix;
                        for (int i = 0; i < k; i++) {
                            unsigned u = tile[(((int)lst[i]) << 5) | lane];
                            if (((u ^ prefix) >> shift) == 0u) r = u;
                        }
                        if (hasPrev && ((prevU ^ prefix) >> shift) == 0u) r = prevU;
                        if (hasNext && ((nextU ^ prefix) >> shift) == 0u) r = nextU;
                        result = r;
                        done = true;
                    }
                }
                if (!done) result = prefix;
            }
        }

        if (!ovf) {
            if (c == 1) {
                result = buf[tid];
            } else {
                // tiny nibble radix over c (<= SLOTS) buffered survivors
                unsigned prefix = pref8 << 24;
                bool done = false;
                #pragma unroll 1
                for (int p = 2; p < 8; p++) {
                    if (__all_sync(__activemask(), done || c <= 1)) break;
                    const int shift = 28 - 4 * p;
                    if (!done && c > 1) {
                        unsigned long long h0 = 0ull, h1 = 0ull;
                        for (int i = 0; i < c; i++) {
                            unsigned u = buf[i * NTH + tid];
                            HIST(u);
                        }
                        unsigned rem;
                        int g = select_bin(h0, h1, m, rem);
                        prefix |= (unsigned)g << shift;
                        int c2 = 0;
                        for (int i = 0; i < c; i++) {
                            unsigned u = buf[i * NTH + tid];
                            if (((u >> shift) & 15u) == (unsigned)g) { buf[c2 * NTH + tid] = u; c2++; }
                        }
                        c = c2;
                        if (c == 1) { result = buf[tid]; done = true; }
                    }
                }
                if (!done) result = (c == 1) ? buf[tid] : prefix;
            }
        }

        out[(size_t)bt * (Nc * Dc) + n * Dc + lane] = u2f(result);
    }
}

extern "C" void kernel_launch(void* const* d_in, const int* in_sizes, int n_in,
                              void* d_out, int out_size)
{
    const float* xs  = (const float*)d_in[0];
    const int*   A   = (const int*)d_in[1];
    float*       out = (float*)d_out;
    (void)in_sizes; (void)n_in; (void)out_size;

    prep_kernel<<<1, Nc>>>(A);
    median_kernel<<<Bc * Tc * 8, NTH>>>(xs, out);
}

// round 5
// speedup vs baseline: 1.8909x; 1.8909x over previous
#include <cuda_runtime.h>

// MedianFilter: xs [B=4,T=32,N=128,D=32] f32, A [1,128,128] i32.
// Per (b,t,n,d): lower median over {prev-self (t>0), next-self (t<T-1),
//   xs[b,t,j,d] for j with (A+I)[n][j]!=0}.
// Exact MSB-first radix-select: nibble hist @28, filtered nibble hist @24,
// collect 8-bit-prefix matches, tiny radix tail. Masked/pad candidates are
// dummy max-keys (== reference's +inf padding) so all loops are uniform.

#define Bc 4
#define Tc 32
#define Nc 128
#define Dc 32
#define NTH 512          // threads/block, 16 warps, 1 warp = 1 node
#define NODES_PB 16
#define SLOTS 20
#define ROWP 132         // padded spatial list stride (multiple of 4)
#define DUMMY_ROW 128

typedef unsigned long long u64;

__device__ unsigned char g_nbr[Nc * ROWP];
__device__ int g_cnt[Nc];

__device__ __forceinline__ unsigned f2u(float f) {
    unsigned s = __float_as_uint(f);
    return s ^ ((unsigned)((int)s >> 31) | 0x80000000u);
}
__device__ __forceinline__ float u2f(unsigned u) {
    unsigned s = (u & 0x80000000u) ? (u ^ 0x80000000u) : ~u;
    return __uint_as_float(s);
}

// bin containing rank m from byte-packed histograms B0(bins0-7)/B1(8-15);
// total count <= ~135 so bytes never overflow. Updates m to within-bin rank;
// rem = bin count.
__device__ __forceinline__ int select_bin(u64 B0, u64 B1,
                                          unsigned &m, unsigned &rem)
{
    u64 s0 = B0 * 0x0101010101010101ull;
    unsigned tot0 = (unsigned)(s0 >> 56);
    u64 S, H;
    int base;
    unsigned mm = m;
    if (mm < tot0) { S = s0; H = B0; base = 0; }
    else { mm -= tot0; S = B1 * 0x0101010101010101ull; H = B1; base = 8; }
    int g = 0;
    if ((unsigned)((S >> 24) & 0xFF) <= mm) g = 4;
    if ((unsigned)((S >> (8 * (g + 1))) & 0xFF) <= mm) g += 2;
    if ((unsigned)((S >> (8 * g)) & 0xFF) <= mm) g += 1;
    unsigned before = g ? (unsigned)((S >> (8 * (g - 1))) & 0xFF) : 0u;
    rem = (unsigned)((H >> (8 * g)) & 0xFF);
    m = mm - before;
    return base + g;
}

// expand nibble-packed h (16 x 4-bit) into byte-packed B0/B1
#define FLUSH(h_, B0_, B1_)                                                  \
    {                                                                        \
        unsigned lo_ = (unsigned)(h_), hi_ = (unsigned)((h_) >> 32);         \
        unsigned e0_ = lo_ & 0x0F0F0F0Fu, o0_ = (lo_ >> 4) & 0x0F0F0F0Fu;    \
        unsigned e1_ = hi_ & 0x0F0F0F0Fu, o1_ = (hi_ >> 4) & 0x0F0F0F0Fu;    \
        B0_ += ((u64)__byte_perm(e0_, o0_, 0x7362) << 32) |                  \
               (u64)__byte_perm(e0_, o0_, 0x5140);                           \
        B1_ += ((u64)__byte_perm(e1_, o1_, 0x7362) << 32) |                  \
               (u64)__byte_perm(e1_, o1_, 0x5140);                           \
    }

// fallback: old-style filtered byte-packed hist (counts only matching prefix)
#define HISTF(u_)                                                            \
    {                                                                        \
        unsigned uu_ = (u_);                                                 \
        bool ma_ = ((uu_ ^ prefix) >> (shift + 4)) == 0u;                    \
        unsigned nib_ = (uu_ >> shift) & 15u;                                \
        u64 inc_ = ma_ ? (1ull << ((nib_ & 7u) * 8u)) : 0ull;                \
        if (nib_ & 8u) B1 += inc_; else B0 += inc_;                          \
    }

__global__ void prep_kernel(const int* __restrict__ A)
{
    __shared__ int wcnt[4];
    const int n = blockIdx.x;
    const int j = threadIdx.x;
    const int w = j >> 5, lane = j & 31;
    bool v = (A[n * Nc + j] != 0) || (j == n);
    unsigned mask = __ballot_sync(0xFFFFFFFFu, v);
    if (lane == 0) wcnt[w] = __popc(mask);
    __syncthreads();
    int base = 0;
    for (int i = 0; i < w; i++) base += wcnt[i];
    int off = base + __popc(mask & ((1u << lane) - 1u));
    if (v) g_nbr[n * ROWP + off] = (unsigned char)j;
    int tot = wcnt[0] + wcnt[1] + wcnt[2] + wcnt[3];
    if (j == 0) g_cnt[n] = tot;
    int padded = (tot + 3) & ~3;
    if (j >= tot && j < padded) g_nbr[n * ROWP + j] = (unsigned char)DUMMY_ROW;
}

extern __shared__ unsigned buf[];   // SLOTS * NTH words = 40KB

__global__ __launch_bounds__(NTH, 3)
void median_kernel(const float* __restrict__ xs, float* __restrict__ out)
{
    __shared__ unsigned tile[(Nc + 1) * Dc];         // 16.5KB (+dummy row)
    __shared__ unsigned char nbr[NODES_PB * ROWP];   // 2.1KB
    __shared__ int cnt[NODES_PB];

    const int bid  = blockIdx.x;
    const int bt   = bid >> 3;
    const int oct  = bid & 7;
    const int t    = bt & (Tc - 1);
    const int tid  = threadIdx.x;
    const int lane = tid & 31;
    const int w    = tid >> 5;            // warp = local node
    const int n    = oct * NODES_PB + w;

    const float* cur = xs + (size_t)bt * (Nc * Dc);
    #pragma unroll
    for (int i = tid; i < Nc * Dc; i += NTH) tile[i] = f2u(cur[i]);
    if (tid < Dc) tile[Nc * Dc + tid] = 0xFFFFFFFFu;

    {
        const unsigned* src = (const unsigned*)&g_nbr[(oct * NODES_PB) * ROWP];
        unsigned* dst = (unsigned*)nbr;
        #pragma unroll
        for (int i = tid; i < NODES_PB * ROWP / 4; i += NTH) dst[i] = src[i];
        if (tid < NODES_PB) cnt[tid] = g_cnt[oct * NODES_PB + tid];
    }
    __syncthreads();

    const bool hasPrev = (t > 0);
    const bool hasNext = (t < Tc - 1);
    const float* prevp = xs + (size_t)(hasPrev ? bt - 1 : bt) * (Nc * Dc);
    const float* nextp = xs + (size_t)(hasNext ? bt + 1 : bt) * (Nc * Dc);

    const int k  = cnt[w];
    const int kq = (k + 3) >> 2;
    const unsigned* lstw = (const unsigned*)&nbr[w * ROWP];
    unsigned m = (unsigned)((k + (int)hasPrev + (int)hasNext - 1) >> 1);

    unsigned prevU = 0xFFFFFFFFu, nextU = 0xFFFFFFFFu;
    if (hasPrev) prevU = f2u(prevp[n * Dc + lane]);
    if (hasNext) nextU = f2u(nextp[n * Dc + lane]);

    unsigned rem;

    // ---------- scan 1: unfiltered nibble hist @28 ----------
    unsigned g1;
    {
        u64 B0 = 0ull, B1 = 0ull;
        u64 h = (1ull << ((prevU >> 26) & 0x3Cu))
              + (1ull << ((nextU >> 26) & 0x3Cu));
        int q = 0;
        while (q < kq) {
            int qe = min(q + 3, kq);          // <=12 per chunk (+2 first)
            for (; q < qe; q++) {
                unsigned w4 = lstw[q];
                #pragma unroll
                for (int s = 0; s < 4; s++) {
                    unsigned idx = (w4 >> (8 * s)) & 255u;
                    unsigned u = tile[(idx << 5) | lane];
                    h += 1ull << ((u >> 26) & 0x3Cu);
                }
            }
            FLUSH(h, B0, B1);
            h = 0ull;
        }
        g1 = (unsigned)select_bin(B0, B1, m, rem);
    }

    // ---------- scan 2: nibble hist @24 filtered on top nibble ----------
    unsigned g2;
    {
        const unsigned pfx = g1 << 28;
        u64 B0 = 0ull, B1 = 0ull;
        u64 h = 0ull;
        if ((prevU ^ pfx) < (1u << 28)) h += 1ull << ((prevU >> 22) & 0x3Cu);
        if ((nextU ^ pfx) < (1u << 28)) h += 1ull << ((nextU >> 22) & 0x3Cu);
        int q = 0;
        while (q < kq) {
            int qe = min(q + 3, kq);
            for (; q < qe; q++) {
                unsigned w4 = lstw[q];
                #pragma unroll
                for (int s = 0; s < 4; s++) {
                    unsigned idx = (w4 >> (8 * s)) & 255u;
                    unsigned u = tile[(idx << 5) | lane];
                    if ((u ^ pfx) < (1u << 28)) h += 1ull << ((u >> 22) & 0x3Cu);
                }
            }
            FLUSH(h, B0, B1);
            h = 0ull;
        }
        g2 = (unsigned)select_bin(B0, B1, m, rem);
    }
    const unsigned pref8 = (g1 << 4) | g2;

    // ---------- collect 8-bit-prefix matches ----------
    int c = 0;
    {
        unsigned* bslot = buf + tid;
        for (int q = 0; q < kq; q++) {
            unsigned w4 = lstw[q];
            #pragma unroll
            for (int s = 0; s < 4; s++) {
                unsigned idx = (w4 >> (8 * s)) & 255u;
                unsigned u = tile[(idx << 5) | lane];
                if ((u >> 24) == pref8) {
                    if (c < SLOTS) bslot[c * NTH] = u;
                    c++;
                }
            }
        }
        if ((prevU >> 24) == pref8) { if (c < SLOTS) bslot[c * NTH] = prevU; c++; }
        if ((nextU >> 24) == pref8) { if (c < SLOTS) bslot[c * NTH] = nextU; c++; }
    }

    unsigned result = 0;
    const bool ovf = (c > SLOTS);

    if (__any_sync(0xFFFFFFFFu, ovf)) {
        // ---- exact cold fallback: filtered full scans on lower nibbles ----
        if (ovf) {
            unsigned prefix = pref8 << 24;
            bool done = false;
            #pragma unroll 1
            for (int p = 2; p < 8 && !done; p++) {
                const int shift = 28 - 4 * p;
                u64 B0 = 0ull, B1 = 0ull;
                for (int i = 0; i < k; i++) {
                    unsigned idx = ((const unsigned char*)lstw)[i];
                    unsigned u = tile[(idx << 5) | lane];
                    HISTF(u);
                }
                HISTF(prevU);
                HISTF(nextU);
                int g = select_bin(B0, B1, m, rem);
                prefix |= (unsigned)g << shift;
                if (rem == 1u) {
                    unsigned r = prefix;
                    for (int i = 0; i < k; i++) {
                        unsigned idx = ((const unsigned char*)lstw)[i];
                        unsigned u = tile[(idx << 5) | lane];
                        if (((u ^ prefix) >> shift) == 0u) r = u;
                    }
                    if (((prevU ^ prefix) >> shift) == 0u) r = prevU;
                    if (((nextU ^ prefix) >> shift) == 0u) r = nextU;
                    result = r;
                    done = true;
                }
            }
            if (!done) result = prefix;
        }
    }

    if (!ovf) {
        // ---------- tiny radix tail over c (<= SLOTS) buffered survivors ----
        unsigned* bslot = buf + tid;
        int shift = 20;
        #pragma unroll 1
        while (__any_sync(0xFFFFFFFFu, c > 1) && shift >= 0) {
            if (c > 1) {
                u64 B0 = 0ull, B1 = 0ull;
                int i = 0;
                while (i < c) {
                    int ie = min(i + 15, c);
                    u64 h = 0ull;
                    for (; i < ie; i++) {
                        unsigned u = bslot[i * NTH];
                        h += 1ull << (((u >> shift) & 15u) << 2);
                    }
                    FLUSH(h, B0, B1);
                }
                int g = select_bin(B0, B1, m, rem);
                int c2 = 0;
                for (int i2 = 0; i2 < c; i2++) {
                    unsigned u = bslot[i2 * NTH];
                    if (((u >> shift) & 15u) == (unsigned)g) { bslot[c2 * NTH] = u; c2++; }
                }
                c = c2;
            }
            shift -= 4;
        }
        result = bslot[0];
    }

    out[(size_t)bt * (Nc * Dc) + n * Dc + lane] = u2f(result);
}

extern "C" void kernel_launch(void* const* d_in, const int* in_sizes, int n_in,
                              void* d_out, int out_size)
{
    const float* xs  = (const float*)d_in[0];
    const int*   A   = (const int*)d_in[1];
    float*       out = (float*)d_out;
    (void)in_sizes; (void)n_in; (void)out_size;

    cudaFuncSetAttribute(median_kernel,
                         cudaFuncAttributeMaxDynamicSharedMemorySize,
                         SLOTS * NTH * 4);
    prep_kernel<<<Nc, Nc>>>(A);
    median_kernel<<<Bc * Tc * 8, NTH, SLOTS * NTH * 4>>>(xs, out);
}